// round 15
// baseline (speedup 1.0000x reference)
#include <cuda_runtime.h>
#include <cuda_bf16.h>
#include <math.h>
#include <stdint.h>

// ---------------- problem constants ----------------
#define BB   16
#define SS   1024
#define DIN  768
#define EE   512
#define HH   8
#define LL   2
#define FF   2048
#define DH   64
#define MTOK (BB*SS)          // 16384 rows

// ---------------- scratch ----------------
__device__ float g_x  [MTOK*EE];
__device__ float g_a  [MTOK*EE];
__device__ float g_qkv[MTOK*3*EE];
__device__ float g_o  [MTOK*EE];
__device__ float g_f  [MTOK*FF];
__device__ float g_xp [MTOK*EE];
__device__ float g_h  [BB*EE];
__device__ float g_wr [7208960];        // tf32-rounded weight copies

// rounded-weight offsets
#define OFF_WP   0
#define OFF_WQKV 393216
#define OFF_WO   1966080
#define OFF_W1   2490368
#define OFF_W2   4587520
#define OFF_WI   6684672
#define WR_TOTAL 7208960

// ---------------- helpers ----------------
__device__ __forceinline__ float gelu_exact(float x) {
    return 0.5f * x * (1.0f + erff(x * 0.7071067811865476f));
}
__device__ __forceinline__ uint32_t swz128(uint32_t off) {
    return off ^ ((off >> 3) & 0x70);
}
__device__ __forceinline__ void cpasync16(uint32_t dst, const void* src) {
    asm volatile("cp.async.cg.shared.global [%0], [%1], 16;" :: "r"(dst), "l"(src));
}
__device__ __forceinline__ void cp_commit() { asm volatile("cp.async.commit_group;"); }
__device__ __forceinline__ void cp_wait1() { asm volatile("cp.async.wait_group 1;"); }
__device__ __forceinline__ void cp_wait0() { asm volatile("cp.async.wait_group 0;"); }
__device__ __forceinline__ uint32_t smem_u32(const void* p) {
    uint32_t a;
    asm("{ .reg .u64 t; cvta.to.shared.u64 t, %1; cvt.u32.u64 %0, t; }" : "=r"(a) : "l"(p));
    return a;
}
__device__ __forceinline__ uint32_t f2tf(float f) {
    uint32_t u;
    asm("cvt.rna.tf32.f32 %0, %1;" : "=r"(u) : "f"(f));
    return u;
}
__device__ __forceinline__ float roundtf(float f) {
    return __uint_as_float(f2tf(f));
}
__device__ __forceinline__ float lds_swz(const char* base, int row, int col) {
    return *(const float*)(base + row * 128 + ((col * 4) ^ ((row & 7) << 4)));
}
__device__ __forceinline__ void mma_tf32(float* c, const uint32_t* a, const uint32_t* b) {
    asm volatile(
        "mma.sync.aligned.m16n8k8.row.col.f32.tf32.tf32.f32 "
        "{%0,%1,%2,%3}, {%4,%5,%6,%7}, {%8,%9}, {%0,%1,%2,%3};"
        : "+f"(c[0]), "+f"(c[1]), "+f"(c[2]), "+f"(c[3])
        : "r"(a[0]), "r"(a[1]), "r"(a[2]), "r"(a[3]), "r"(b[0]), "r"(b[1]));
}

// =====================================================================
// Single merged weight-prep launch: round all six weight tensors.
// =====================================================================
__global__ void round_all_kernel(const float* __restrict__ s0, const float* __restrict__ s1,
                                 const float* __restrict__ s2, const float* __restrict__ s3,
                                 const float* __restrict__ s4, const float* __restrict__ s5,
                                 float* __restrict__ dst)
{
    int i = blockIdx.x * 256 + threadIdx.x;
    if (i >= WR_TOTAL) return;
    const float* src; int off;
    if      (i < OFF_WQKV) { src = s0; off = i - OFF_WP;   }
    else if (i < OFF_WO)   { src = s1; off = i - OFF_WQKV; }
    else if (i < OFF_W1)   { src = s2; off = i - OFF_WO;   }
    else if (i < OFF_W2)   { src = s3; off = i - OFF_W1;   }
    else if (i < OFF_WI)   { src = s4; off = i - OFF_W2;   }
    else                   { src = s5; off = i - OFF_WI;   }
    dst[i] = roundtf(src[off]);
}

// =====================================================================
// tf32 warp-MMA GEMM (R8 champion version, unchanged):
//   C[M,N] = epi( A[M,K] * B^T + bias ); B pre-rounded (g_wr).
//   CVTA: cvt A frags in-loop (raw f32 A); RND: round outputs.
//   EPI: 0=bias, 1=bias+gelu, 2=C += acc + bias.
// =====================================================================
template<int EPI, bool CVTA, bool RND>
__global__ void __launch_bounds__(256, 2)
gemm_mma(const float* __restrict__ A, const float* __restrict__ B,
         const float* __restrict__ bias, float* __restrict__ C,
         int M, int N, int K, int lda, int ldb, int ldc)
{
    extern __shared__ char smem[];
    constexpr int ASZ = 128 * 32 * 4;
    constexpr int BSZ = 128 * 32 * 4;
    const uint32_t sb = smem_u32(smem);

    const int tid = threadIdx.x;
    const int wid = tid >> 5;
    const int lane = tid & 31;
    const int g  = lane >> 2;
    const int tg = lane & 3;
    const int wm = wid & 3;
    const int wn = wid >> 2;
    const int bm = blockIdx.y * 128;
    const int bn = blockIdx.x * 128;

    const int NC = K >> 5;

    float acc[2][8][4];
    #pragma unroll
    for (int i = 0; i < 2; i++)
        #pragma unroll
        for (int j = 0; j < 8; j++)
            #pragma unroll
            for (int q = 0; q < 4; q++) acc[i][j][q] = 0.f;

    auto loadA = [&](int stage, int k0) {
        uint32_t base = sb + stage * (ASZ + BSZ);
        const float* src0 = A + (long long)bm * lda + k0;
        #pragma unroll
        for (int i = 0; i < 4; i++) {
            int j = tid + i * 256;
            int row = j >> 3;
            int c4  = (j & 7) * 4;
            cpasync16(base + swz128(row * 128 + c4 * 4),
                      src0 + (long long)row * lda + c4);
        }
    };
    auto loadB = [&](int stage, int k0) {
        uint32_t base = sb + stage * (ASZ + BSZ) + ASZ;
        const float* src0 = B + (long long)bn * ldb + k0;
        #pragma unroll
        for (int i = 0; i < 4; i++) {
            int j = tid + i * 256;
            int row = j >> 3;
            int c4  = (j & 7) * 4;
            cpasync16(base + swz128(row * 128 + c4 * 4),
                      src0 + (long long)row * ldb + c4);
        }
    };

    auto compute = [&](int stage) {
        const char* Ab = smem + stage * (ASZ + BSZ);
        const char* Bb = Ab + ASZ;
        #pragma unroll
        for (int kk = 0; kk < 4; kk++) {
            const int k0 = kk * 8;
            uint32_t afr[2][4];
            #pragma unroll
            for (int ma = 0; ma < 2; ma++) {
                int r0 = wm * 32 + ma * 16 + g;
                if (CVTA) {
                    afr[ma][0] = f2tf(lds_swz(Ab, r0,     k0 + tg));
                    afr[ma][1] = f2tf(lds_swz(Ab, r0 + 8, k0 + tg));
                    afr[ma][2] = f2tf(lds_swz(Ab, r0,     k0 + tg + 4));
                    afr[ma][3] = f2tf(lds_swz(Ab, r0 + 8, k0 + tg + 4));
                } else {
                    afr[ma][0] = __float_as_uint(lds_swz(Ab, r0,     k0 + tg));
                    afr[ma][1] = __float_as_uint(lds_swz(Ab, r0 + 8, k0 + tg));
                    afr[ma][2] = __float_as_uint(lds_swz(Ab, r0,     k0 + tg + 4));
                    afr[ma][3] = __float_as_uint(lds_swz(Ab, r0 + 8, k0 + tg + 4));
                }
            }
            uint32_t bfr[8][2];
            #pragma unroll
            for (int na = 0; na < 8; na++) {
                int rn = wn * 64 + na * 8 + g;
                bfr[na][0] = __float_as_uint(lds_swz(Bb, rn, k0 + tg));
                bfr[na][1] = __float_as_uint(lds_swz(Bb, rn, k0 + tg + 4));
            }
            #pragma unroll
            for (int ma = 0; ma < 2; ma++)
                #pragma unroll
                for (int na = 0; na < 8; na++)
                    mma_tf32(acc[ma][na], afr[ma], bfr[na]);
        }
    };

    // ---------- 3-stage pipelined mainloop ----------
    loadA(0, 0); loadB(0, 0); cp_commit();
    loadA(1, 32); loadB(1, 32); cp_commit();
    for (int c = 0; c < NC; c++) {
        if (c + 1 < NC) cp_wait1(); else cp_wait0();
        __syncthreads();
        if (c + 2 < NC) {
            int s = (c + 2) % 3;
            loadA(s, (c + 2) << 5); loadB(s, (c + 2) << 5); cp_commit();
        }
        compute(c % 3);
    }

    // ---------- epilogue ----------
    #pragma unroll
    for (int ma = 0; ma < 2; ma++) {
        int row0 = bm + wm * 32 + ma * 16 + g;
        #pragma unroll
        for (int na = 0; na < 8; na++) {
            int col = bn + wn * 64 + na * 8 + tg * 2;
            #pragma unroll
            for (int half = 0; half < 2; half++) {
                int row = row0 + half * 8;
                float2 v;
                v.x = acc[ma][na][half * 2 + 0];
                v.y = acc[ma][na][half * 2 + 1];
                if (bias) { v.x += bias[col]; v.y += bias[col + 1]; }
                if (EPI == 1) { v.x = gelu_exact(v.x); v.y = gelu_exact(v.y); }
                if (RND) { v.x = roundtf(v.x); v.y = roundtf(v.y); }
                long long ro = (long long)row * ldc;
                if (EPI == 2) {
                    float2 old = *(const float2*)(C + ro + col);
                    v.x += old.x; v.y += old.y;
                }
                *(float2*)(C + ro + col) = v;
            }
        }
    }
}

// =====================================================================
// Fused flash attention (R8/R11 measured version, unchanged).
// =====================================================================
#define KST 68
#define VST 72
#define PST 132
#define FKSZ (128*KST*4)
#define FVSZ (128*VST*4)
#define FL_SMEM (2*FKSZ + 2*FVSZ + 128*PST*4)

__global__ void __launch_bounds__(256, 1)
flash_kernel(const float* __restrict__ qkv, float* __restrict__ o)
{
    extern __shared__ char fs[];
    const int tid = threadIdx.x;
    const int w = tid >> 5, lane = tid & 31;
    const int g = lane >> 2, tg = lane & 3;
    const int qt = blockIdx.x;
    const int z  = blockIdx.y;
    const int bb = z >> 3, hh = z & 7;

    char* Ks = fs;
    char* Vs = fs + 2 * FKSZ;
    float* Ps = (float*)(fs + 2 * FKSZ + 2 * FVSZ);
    const uint32_t Ksb = smem_u32(Ks), Vsb = smem_u32(Vs);

    const float* qbase = qkv + (size_t)bb * SS * (3 * EE) + hh * DH;

    uint32_t qfr[8][4];
    {
        int r0 = qt * 128 + w * 16 + g;
        const float* q0 = qbase + (size_t)r0 * (3 * EE);
        const float* q1 = q0 + (size_t)8 * (3 * EE);
        #pragma unroll
        for (int kk = 0; kk < 8; kk++) {
            qfr[kk][0] = __float_as_uint(0.125f * q0[kk * 8 + tg]);
            qfr[kk][1] = __float_as_uint(0.125f * q1[kk * 8 + tg]);
            qfr[kk][2] = __float_as_uint(0.125f * q0[kk * 8 + tg + 4]);
            qfr[kk][3] = __float_as_uint(0.125f * q1[kk * 8 + tg + 4]);
        }
    }

    float m0 = -1e30f, m1 = -1e30f, l0 = 0.f, l1 = 0.f;
    float oacc[8][4];
    #pragma unroll
    for (int i = 0; i < 8; i++)
        #pragma unroll
        for (int q = 0; q < 4; q++) oacc[i][q] = 0.f;

    auto loadKV = [&](int st, int j) {
        const float* kg = qbase + EE     + (size_t)(j * 128) * (3 * EE);
        const float* vg = qbase + 2 * EE + (size_t)(j * 128) * (3 * EE);
        #pragma unroll
        for (int i = 0; i < 8; i++) {
            int idx = tid + i * 256;
            int row = idx >> 4, c4 = (idx & 15) * 4;
            cpasync16(Ksb + st * FKSZ + (row * KST + c4) * 4,
                      kg + (size_t)row * (3 * EE) + c4);
            cpasync16(Vsb + st * FVSZ + (row * VST + c4) * 4,
                      vg + (size_t)row * (3 * EE) + c4);
        }
    };

    loadKV(0, 0); cp_commit();

    const int prow0 = (w * 16 + g) * PST;
    const int prow1 = prow0 + 8 * PST;

    for (int j = 0; j < 8; j++) {
        cp_wait0();
        __syncthreads();
        if (j + 1 < 8) { loadKV((j + 1) & 1, j + 1); cp_commit(); }

        float sacc[16][4];
        #pragma unroll
        for (int na = 0; na < 16; na++)
            #pragma unroll
            for (int q = 0; q < 4; q++) sacc[na][q] = 0.f;

        const float* Kt = (const float*)(Ks + (j & 1) * FKSZ);
        #pragma unroll
        for (int kk = 0; kk < 8; kk++) {
            #pragma unroll
            for (int na = 0; na < 16; na++) {
                int rn = na * 8 + g;
                uint32_t bfr[2];
                bfr[0] = __float_as_uint(Kt[rn * KST + kk * 8 + tg]);
                bfr[1] = __float_as_uint(Kt[rn * KST + kk * 8 + tg + 4]);
                mma_tf32(sacc[na], qfr[kk], bfr);
            }
        }

        float mx0 = -1e30f, mx1 = -1e30f;
        #pragma unroll
        for (int na = 0; na < 16; na++) {
            mx0 = fmaxf(mx0, fmaxf(sacc[na][0], sacc[na][1]));
            mx1 = fmaxf(mx1, fmaxf(sacc[na][2], sacc[na][3]));
        }
        mx0 = fmaxf(mx0, __shfl_xor_sync(0xffffffffu, mx0, 1));
        mx0 = fmaxf(mx0, __shfl_xor_sync(0xffffffffu, mx0, 2));
        mx1 = fmaxf(mx1, __shfl_xor_sync(0xffffffffu, mx1, 1));
        mx1 = fmaxf(mx1, __shfl_xor_sync(0xffffffffu, mx1, 2));
        float nm0 = fmaxf(m0, mx0), nm1 = fmaxf(m1, mx1);
        float a0 = expf(m0 - nm0), a1 = expf(m1 - nm1);
        float rs0 = 0.f, rs1 = 0.f;
        #pragma unroll
        for (int na = 0; na < 16; na++) {
            float p00 = expf(sacc[na][0] - nm0);
            float p01 = expf(sacc[na][1] - nm0);
            float p10 = expf(sacc[na][2] - nm1);
            float p11 = expf(sacc[na][3] - nm1);
            rs0 += p00 + p01; rs1 += p10 + p11;
            int col = na * 8 + tg * 2;
            *(float2*)(Ps + prow0 + col) = make_float2(roundtf(p00), roundtf(p01));
            *(float2*)(Ps + prow1 + col) = make_float2(roundtf(p10), roundtf(p11));
        }
        rs0 += __shfl_xor_sync(0xffffffffu, rs0, 1);
        rs0 += __shfl_xor_sync(0xffffffffu, rs0, 2);
        rs1 += __shfl_xor_sync(0xffffffffu, rs1, 1);
        rs1 += __shfl_xor_sync(0xffffffffu, rs1, 2);
        l0 = l0 * a0 + rs0; l1 = l1 * a1 + rs1;
        m0 = nm0; m1 = nm1;
        #pragma unroll
        for (int na2 = 0; na2 < 8; na2++) {
            oacc[na2][0] *= a0; oacc[na2][1] *= a0;
            oacc[na2][2] *= a1; oacc[na2][3] *= a1;
        }
        __syncthreads();

        const float* Vt = (const float*)(Vs + (j & 1) * FVSZ);
        #pragma unroll
        for (int kk = 0; kk < 16; kk++) {
            uint32_t pf[4];
            pf[0] = __float_as_uint(Ps[prow0 + kk * 8 + tg]);
            pf[1] = __float_as_uint(Ps[prow1 + kk * 8 + tg]);
            pf[2] = __float_as_uint(Ps[prow0 + kk * 8 + tg + 4]);
            pf[3] = __float_as_uint(Ps[prow1 + kk * 8 + tg + 4]);
            #pragma unroll
            for (int na2 = 0; na2 < 8; na2++) {
                uint32_t bf[2];
                bf[0] = __float_as_uint(Vt[(kk * 8 + tg) * VST + na2 * 8 + g]);
                bf[1] = __float_as_uint(Vt[(kk * 8 + tg + 4) * VST + na2 * 8 + g]);
                mma_tf32(oacc[na2], pf, bf);
            }
        }
    }

    float inv0 = 1.f / l0, inv1 = 1.f / l1;
    int r0 = qt * 128 + w * 16 + g;
    float* ob0 = o + (size_t)(bb * SS + r0) * EE + hh * DH;
    float* ob1 = ob0 + (size_t)8 * EE;
    #pragma unroll
    for (int na2 = 0; na2 < 8; na2++) {
        int col = na2 * 8 + tg * 2;
        *(float2*)(ob0 + col) = make_float2(roundtf(oacc[na2][0] * inv0),
                                            roundtf(oacc[na2][1] * inv0));
        *(float2*)(ob1 + col) = make_float2(roundtf(oacc[na2][2] * inv1),
                                            roundtf(oacc[na2][3] * inv1));
    }
}

// =====================================================================
// LayerNorm (R8 version): output tf32-rounded, standard layout.
// =====================================================================
__global__ void ln_kernel(const float* __restrict__ x, const float* __restrict__ g,
                          const float* __restrict__ b, float* __restrict__ y)
{
    long long row = blockIdx.x;
    const float* xr = x + row * EE;
    int tid = threadIdx.x;
    float4 v = *(const float4*)(xr + tid * 4);
    float s  = v.x + v.y + v.z + v.w;
    float s2 = v.x * v.x + v.y * v.y + v.z * v.z + v.w * v.w;
    #pragma unroll
    for (int o = 16; o > 0; o >>= 1) {
        s  += __shfl_xor_sync(0xffffffffu, s, o);
        s2 += __shfl_xor_sync(0xffffffffu, s2, o);
    }
    __shared__ float ss[4], ssq[4];
    int w = tid >> 5, l = tid & 31;
    if (l == 0) { ss[w] = s; ssq[w] = s2; }
    __syncthreads();
    s  = ss[0] + ss[1] + ss[2] + ss[3];
    s2 = ssq[0] + ssq[1] + ssq[2] + ssq[3];
    float m   = s * (1.0f / EE);
    float var = s2 * (1.0f / EE) - m * m;
    float inv = rsqrtf(var + 1e-5f);
    float4 gg = *(const float4*)(g + tid * 4);
    float4 bb = *(const float4*)(b + tid * 4);
    float4 o4;
    o4.x = roundtf((v.x - m) * inv * gg.x + bb.x);
    o4.y = roundtf((v.y - m) * inv * gg.y + bb.y);
    o4.z = roundtf((v.z - m) * inv * gg.z + bb.z);
    o4.w = roundtf((v.w - m) * inv * gg.w + bb.w);
    *(float4*)(y + row * EE + tid * 4) = o4;
}

// =====================================================================
// Mamba-style recurrence v3: feature=tid>>2, part=tid&3.
// Warp-local shuffle reduction replaces the smem partial round-trip +
// __syncthreads per step. h reads rotated by part (j=(i+p)&31) so the
// 4 parts' LDS.128 hit disjoint banks (8-way broadcast within feature).
// =====================================================================
__global__ void __cluster_dims__(8, 1, 1) __launch_bounds__(256, 1)
recur_kernel(const float* __restrict__ XP, const float* __restrict__ h0,
             const float* __restrict__ Wi2h, float* __restrict__ hout)
{
    __shared__ float hbuf[2 * EE];

    const int tid = threadIdx.x;
    const int b = blockIdx.x >> 3;
    const int r = blockIdx.x & 7;
    const int f = tid >> 2;            // feature 0..63
    const int p = tid & 3;             // k-part 0..3

    float4 w[32];
    {
        const float* wsrc = Wi2h + (long long)(r * 64 + f) * (2 * EE) + EE + p * 128;
        #pragma unroll
        for (int i = 0; i < 32; i++) w[i] = *(const float4*)(wsrc + i * 4);
    }
    if (tid < 128) *(float4*)(hbuf + tid * 4) = *(const float4*)(h0 + b * EE + tid * 4);

    uint32_t hb = (uint32_t)__cvta_generic_to_shared(hbuf);
    __syncthreads();
    asm volatile("barrier.cluster.arrive.aligned;" ::: "memory");
    asm volatile("barrier.cluster.wait.aligned;"   ::: "memory");

    const long long xpbase = (long long)b * SS * EE + r * 64 + f;

    for (int t = 0; t < SS; t++) {
        float xpv = 0.f;
        if (p == 0) xpv = __ldg(XP + xpbase + (long long)t * EE);

        const float* hr = hbuf + (t & 1) * EE + p * 128;
        float a0 = 0.f, a1 = 0.f, a2 = 0.f, a3 = 0.f;
        #pragma unroll
        for (int i = 0; i < 32; i++) {
            int j = (i + p) & 31;                       // part-rotated: bank-disjoint
            float4 h4 = *(const float4*)(hr + j * 4);
            a0 += w[j].x * h4.x; a1 += w[j].y * h4.y;
            a2 += w[j].z * h4.z; a3 += w[j].w * h4.w;
        }
        float sm = (a0 + a1) + (a2 + a3);
        sm += __shfl_xor_sync(0xffffffffu, sm, 1);
        sm += __shfl_xor_sync(0xffffffffu, sm, 2);

        if (p == 0) {
            sm += xpv;
            float hn = tanhf(sm);
            hn = (hn > 0.f) ? hn : 0.f;
            uint32_t loff = hb + (uint32_t)((((t + 1) & 1) * EE + r * 64 + f) * 4);
            #pragma unroll
            for (int c = 0; c < 8; c++) {
                uint32_t ra;
                asm("mapa.shared::cluster.u32 %0, %1, %2;" : "=r"(ra) : "r"(loff), "r"(c));
                asm volatile("st.shared::cluster.f32 [%0], %1;" :: "r"(ra), "f"(hn));
            }
        }
        asm volatile("barrier.cluster.arrive.aligned;" ::: "memory");
        asm volatile("barrier.cluster.wait.aligned;"   ::: "memory");
    }
    if (p == 0) hout[b * EE + r * 64 + f] = hbuf[r * 64 + f];
}

// =====================================================================
// Head (unchanged).
// =====================================================================
__global__ void head_kernel(const float* __restrict__ hfin, const float* __restrict__ Wh2o,
                            const float* __restrict__ bh2o, const float* __restrict__ Wc,
                            const float* __restrict__ bc, float* __restrict__ out, int half)
{
    int b = blockIdx.x, tid = threadIdx.x;
    __shared__ float hrow[EE];
    __shared__ float red[EE];
    hrow[tid] = hfin[b * EE + tid];
    __syncthreads();
    const float* wr = Wh2o + (long long)tid * EE;
    float acc = bh2o[tid];
    #pragma unroll 8
    for (int f = 0; f < EE; f += 4) {
        float4 w4 = *(const float4*)(wr + f);
        acc += w4.x * hrow[f] + w4.y * hrow[f + 1] + w4.z * hrow[f + 2] + w4.w * hrow[f + 3];
    }
    red[tid] = acc * Wc[tid];
    __syncthreads();
    for (int s = 256; s > 0; s >>= 1) {
        if (tid < s) red[tid] += red[tid + s];
        __syncthreads();
    }
    if (tid == 0) {
        float lg = red[0] + bc[0];
        out[b] = lg;
        out[half + b] = 1.f / (1.f + expf(-lg));
    }
}

// ---------------- host-side launch helpers ----------------
static const int GEMM_SMEM = 3 * (128 * 32 * 4 + 128 * 32 * 4);  // 98304

template<int EPI, bool CVTA, bool RND>
static void run_mm(const float* A, const float* B, const float* bias, float* C,
                   int M, int N, int K, int lda, int ldb, int ldc)
{
    cudaFuncSetAttribute(gemm_mma<EPI, CVTA, RND>,
                         cudaFuncAttributeMaxDynamicSharedMemorySize, GEMM_SMEM);
    dim3 grid(N / 128, M / 128, 1);
    gemm_mma<EPI, CVTA, RND><<<grid, 256, GEMM_SMEM>>>(A, B, bias, C, M, N, K, lda, ldb, ldc);
}

extern "C" void kernel_launch(void* const* d_in, const int* in_sizes, int n_in,
                              void* d_out, int out_size)
{
    const float* bm   = (const float*)d_in[0];
    const float* h0   = (const float*)d_in[1];
    const float* Wp   = (const float*)d_in[2];
    const float* bp   = (const float*)d_in[3];
    const float* ln1g = (const float*)d_in[4];
    const float* ln1b = (const float*)d_in[5];
    const float* Wqkv = (const float*)d_in[6];
    const float* bqkv = (const float*)d_in[7];
    const float* Wo   = (const float*)d_in[8];
    const float* bo   = (const float*)d_in[9];
    const float* ln2g = (const float*)d_in[10];
    const float* ln2b = (const float*)d_in[11];
    const float* W1   = (const float*)d_in[12];
    const float* b1   = (const float*)d_in[13];
    const float* W2   = (const float*)d_in[14];
    const float* b2   = (const float*)d_in[15];
    const float* Wi2h = (const float*)d_in[16];
    const float* bi2h = (const float*)d_in[17];
    const float* Wh2o = (const float*)d_in[18];
    const float* bh2o = (const float*)d_in[19];
    const float* Wc   = (const float*)d_in[20];
    const float* bc   = (const float*)d_in[21];
    float* out = (float*)d_out;

    float *px, *pa, *pq, *po, *pf, *pxp, *ph, *pw;
    cudaGetSymbolAddress((void**)&px,  g_x);
    cudaGetSymbolAddress((void**)&pa,  g_a);
    cudaGetSymbolAddress((void**)&pq,  g_qkv);
    cudaGetSymbolAddress((void**)&po,  g_o);
    cudaGetSymbolAddress((void**)&pf,  g_f);
    cudaGetSymbolAddress((void**)&pxp, g_xp);
    cudaGetSymbolAddress((void**)&ph,  g_h);
    cudaGetSymbolAddress((void**)&pw,  g_wr);

    cudaFuncSetAttribute(flash_kernel,
                         cudaFuncAttributeMaxDynamicSharedMemorySize, FL_SMEM);

    // 0) single merged weight-prep launch
    round_all_kernel<<<(WR_TOTAL + 255) / 256, 256>>>(Wp, Wqkv, Wo, W1, W2, Wi2h, pw);

    // 1) modality projection (A raw f32 -> cvt; out = residual f32)
    run_mm<0, true, false>(bm, pw + OFF_WP, bp, px, MTOK, EE, DIN, DIN, DIN, EE);

    for (int l = 0; l < LL; l++) {
        const float* wqkv = pw + OFF_WQKV + (size_t)l * 3 * EE * EE;
        const float* bqk  = bqkv + (size_t)l * 3 * EE;
        const float* wo   = pw + OFF_WO + (size_t)l * EE * EE;
        const float* bo_  = bo   + (size_t)l * EE;
        const float* w1   = pw + OFF_W1 + (size_t)l * FF * EE;
        const float* b1_  = b1   + (size_t)l * FF;
        const float* w2   = pw + OFF_W2 + (size_t)l * EE * FF;
        const float* b2_  = b2   + (size_t)l * EE;

        // pre-LN attention (LN output rounded)
        ln_kernel<<<MTOK, 128>>>(px, ln1g + l * EE, ln1b + l * EE, pa);
        // QKV: A pre-rounded raw bits; output rounded (feeds flash)
        run_mm<0, false, true>(pa, wqkv, bqk, pq, MTOK, 3 * EE, EE, EE, EE, 3 * EE);

        // fused flash attention
        {
            dim3 grid(SS / 128, BB * HH);
            flash_kernel<<<grid, 256, FL_SMEM>>>(pq, po);
        }

        // x += O @ Wo^T + bo
        run_mm<2, false, false>(po, wo, bo_, px, MTOK, EE, EE, EE, EE, EE);

        // pre-LN FFN
        ln_kernel<<<MTOK, 128>>>(px, ln2g + l * EE, ln2b + l * EE, pa);
        run_mm<1, false, true>(pa, w1, b1_, pf, MTOK, FF, EE, EE, EE, FF);
        run_mm<2, false, false>(pf, w2, b2_, px, MTOK, EE, FF, FF, FF, EE);
    }

    // recurrence x-part (A = raw residual f32 -> cvt)
    run_mm<0, true, false>(px, pw + OFF_WI, bi2h, pxp, MTOK, EE, EE, EE, 2 * EE, EE);

    // sequential recurrence (persistent, clustered; original f32 Wi2h)
    recur_kernel<<<128, 256>>>(pxp, h0, Wi2h, ph);

    // head: logits + sigmoid
    head_kernel<<<BB, 512>>>(ph, Wh2o, bh2o, Wc, bc, out, out_size / 2);
}

// round 17
// speedup vs baseline: 1.4039x; 1.4039x over previous
#include <cuda_runtime.h>
#include <cuda_bf16.h>
#include <math.h>
#include <stdint.h>

// ---------------- problem constants ----------------
#define BB   16
#define SS   1024
#define DIN  768
#define EE   512
#define HH   8
#define LL   2
#define FF   2048
#define DH   64
#define MTOK (BB*SS)          // 16384 rows

// ---------------- scratch ----------------
__device__ float g_x  [MTOK*EE];
__device__ float g_a  [MTOK*EE];
__device__ float g_qkv[MTOK*3*EE];
__device__ float g_o  [MTOK*EE];
__device__ float g_f  [MTOK*FF];
__device__ float g_xp [MTOK*EE];
__device__ float g_h  [BB*EE];
__device__ float g_wr [7208960];        // tf32-rounded weight copies

// rounded-weight offsets
#define OFF_WP   0
#define OFF_WQKV 393216
#define OFF_WO   1966080
#define OFF_W1   2490368
#define OFF_W2   4587520
#define OFF_WI   6684672
#define WR_TOTAL 7208960

// ---------------- helpers ----------------
__device__ __forceinline__ float gelu_exact(float x) {
    return 0.5f * x * (1.0f + erff(x * 0.7071067811865476f));
}
__device__ __forceinline__ uint32_t swz128(uint32_t off) {
    return off ^ ((off >> 3) & 0x70);
}
__device__ __forceinline__ void cpasync16(uint32_t dst, const void* src) {
    asm volatile("cp.async.cg.shared.global [%0], [%1], 16;" :: "r"(dst), "l"(src));
}
__device__ __forceinline__ void cp_commit() { asm volatile("cp.async.commit_group;"); }
__device__ __forceinline__ void cp_wait1() { asm volatile("cp.async.wait_group 1;"); }
__device__ __forceinline__ void cp_wait0() { asm volatile("cp.async.wait_group 0;"); }
__device__ __forceinline__ uint32_t smem_u32(const void* p) {
    uint32_t a;
    asm("{ .reg .u64 t; cvta.to.shared.u64 t, %1; cvt.u32.u64 %0, t; }" : "=r"(a) : "l"(p));
    return a;
}
__device__ __forceinline__ uint32_t f2tf(float f) {
    uint32_t u;
    asm("cvt.rna.tf32.f32 %0, %1;" : "=r"(u) : "f"(f));
    return u;
}
__device__ __forceinline__ float roundtf(float f) {
    return __uint_as_float(f2tf(f));
}
__device__ __forceinline__ float lds_swz(const char* base, int row, int col) {
    return *(const float*)(base + row * 128 + ((col * 4) ^ ((row & 7) << 4)));
}
__device__ __forceinline__ void mma_tf32(float* c, const uint32_t* a, const uint32_t* b) {
    asm volatile(
        "mma.sync.aligned.m16n8k8.row.col.f32.tf32.tf32.f32 "
        "{%0,%1,%2,%3}, {%4,%5,%6,%7}, {%8,%9}, {%0,%1,%2,%3};"
        : "+f"(c[0]), "+f"(c[1]), "+f"(c[2]), "+f"(c[3])
        : "r"(a[0]), "r"(a[1]), "r"(a[2]), "r"(a[3]), "r"(b[0]), "r"(b[1]));
}

// =====================================================================
// Single merged weight-prep launch: round all six weight tensors.
// =====================================================================
__global__ void round_all_kernel(const float* __restrict__ s0, const float* __restrict__ s1,
                                 const float* __restrict__ s2, const float* __restrict__ s3,
                                 const float* __restrict__ s4, const float* __restrict__ s5,
                                 float* __restrict__ dst)
{
    int i = blockIdx.x * 256 + threadIdx.x;
    if (i >= WR_TOTAL) return;
    const float* src; int off;
    if      (i < OFF_WQKV) { src = s0; off = i - OFF_WP;   }
    else if (i < OFF_WO)   { src = s1; off = i - OFF_WQKV; }
    else if (i < OFF_W1)   { src = s2; off = i - OFF_WO;   }
    else if (i < OFF_W2)   { src = s3; off = i - OFF_W1;   }
    else if (i < OFF_WI)   { src = s4; off = i - OFF_W2;   }
    else                   { src = s5; off = i - OFF_WI;   }
    dst[i] = roundtf(src[off]);
}

// =====================================================================
// tf32 warp-MMA GEMM (R8 champion version, unchanged).
// =====================================================================
template<int EPI, bool CVTA, bool RND>
__global__ void __launch_bounds__(256, 2)
gemm_mma(const float* __restrict__ A, const float* __restrict__ B,
         const float* __restrict__ bias, float* __restrict__ C,
         int M, int N, int K, int lda, int ldb, int ldc)
{
    extern __shared__ char smem[];
    constexpr int ASZ = 128 * 32 * 4;
    constexpr int BSZ = 128 * 32 * 4;
    const uint32_t sb = smem_u32(smem);

    const int tid = threadIdx.x;
    const int wid = tid >> 5;
    const int lane = tid & 31;
    const int g  = lane >> 2;
    const int tg = lane & 3;
    const int wm = wid & 3;
    const int wn = wid >> 2;
    const int bm = blockIdx.y * 128;
    const int bn = blockIdx.x * 128;

    const int NC = K >> 5;

    float acc[2][8][4];
    #pragma unroll
    for (int i = 0; i < 2; i++)
        #pragma unroll
        for (int j = 0; j < 8; j++)
            #pragma unroll
            for (int q = 0; q < 4; q++) acc[i][j][q] = 0.f;

    auto loadA = [&](int stage, int k0) {
        uint32_t base = sb + stage * (ASZ + BSZ);
        const float* src0 = A + (long long)bm * lda + k0;
        #pragma unroll
        for (int i = 0; i < 4; i++) {
            int j = tid + i * 256;
            int row = j >> 3;
            int c4  = (j & 7) * 4;
            cpasync16(base + swz128(row * 128 + c4 * 4),
                      src0 + (long long)row * lda + c4);
        }
    };
    auto loadB = [&](int stage, int k0) {
        uint32_t base = sb + stage * (ASZ + BSZ) + ASZ;
        const float* src0 = B + (long long)bn * ldb + k0;
        #pragma unroll
        for (int i = 0; i < 4; i++) {
            int j = tid + i * 256;
            int row = j >> 3;
            int c4  = (j & 7) * 4;
            cpasync16(base + swz128(row * 128 + c4 * 4),
                      src0 + (long long)row * ldb + c4);
        }
    };

    auto compute = [&](int stage) {
        const char* Ab = smem + stage * (ASZ + BSZ);
        const char* Bb = Ab + ASZ;
        #pragma unroll
        for (int kk = 0; kk < 4; kk++) {
            const int k0 = kk * 8;
            uint32_t afr[2][4];
            #pragma unroll
            for (int ma = 0; ma < 2; ma++) {
                int r0 = wm * 32 + ma * 16 + g;
                if (CVTA) {
                    afr[ma][0] = f2tf(lds_swz(Ab, r0,     k0 + tg));
                    afr[ma][1] = f2tf(lds_swz(Ab, r0 + 8, k0 + tg));
                    afr[ma][2] = f2tf(lds_swz(Ab, r0,     k0 + tg + 4));
                    afr[ma][3] = f2tf(lds_swz(Ab, r0 + 8, k0 + tg + 4));
                } else {
                    afr[ma][0] = __float_as_uint(lds_swz(Ab, r0,     k0 + tg));
                    afr[ma][1] = __float_as_uint(lds_swz(Ab, r0 + 8, k0 + tg));
                    afr[ma][2] = __float_as_uint(lds_swz(Ab, r0,     k0 + tg + 4));
                    afr[ma][3] = __float_as_uint(lds_swz(Ab, r0 + 8, k0 + tg + 4));
                }
            }
            uint32_t bfr[8][2];
            #pragma unroll
            for (int na = 0; na < 8; na++) {
                int rn = wn * 64 + na * 8 + g;
                bfr[na][0] = __float_as_uint(lds_swz(Bb, rn, k0 + tg));
                bfr[na][1] = __float_as_uint(lds_swz(Bb, rn, k0 + tg + 4));
            }
            #pragma unroll
            for (int ma = 0; ma < 2; ma++)
                #pragma unroll
                for (int na = 0; na < 8; na++)
                    mma_tf32(acc[ma][na], afr[ma], bfr[na]);
        }
    };

    // ---------- 3-stage pipelined mainloop ----------
    loadA(0, 0); loadB(0, 0); cp_commit();
    loadA(1, 32); loadB(1, 32); cp_commit();
    for (int c = 0; c < NC; c++) {
        if (c + 1 < NC) cp_wait1(); else cp_wait0();
        __syncthreads();
        if (c + 2 < NC) {
            int s = (c + 2) % 3;
            loadA(s, (c + 2) << 5); loadB(s, (c + 2) << 5); cp_commit();
        }
        compute(c % 3);
    }

    // ---------- epilogue ----------
    #pragma unroll
    for (int ma = 0; ma < 2; ma++) {
        int row0 = bm + wm * 32 + ma * 16 + g;
        #pragma unroll
        for (int na = 0; na < 8; na++) {
            int col = bn + wn * 64 + na * 8 + tg * 2;
            #pragma unroll
            for (int half = 0; half < 2; half++) {
                int row = row0 + half * 8;
                float2 v;
                v.x = acc[ma][na][half * 2 + 0];
                v.y = acc[ma][na][half * 2 + 1];
                if (bias) { v.x += bias[col]; v.y += bias[col + 1]; }
                if (EPI == 1) { v.x = gelu_exact(v.x); v.y = gelu_exact(v.y); }
                if (RND) { v.x = roundtf(v.x); v.y = roundtf(v.y); }
                long long ro = (long long)row * ldc;
                if (EPI == 2) {
                    float2 old = *(const float2*)(C + ro + col);
                    v.x += old.x; v.y += old.y;
                }
                *(float2*)(C + ro + col) = v;
            }
        }
    }
}

// =====================================================================
// Fused flash attention (R8 measured version, unchanged).
// =====================================================================
#define KST 68
#define VST 72
#define PST 132
#define FKSZ (128*KST*4)
#define FVSZ (128*VST*4)
#define FL_SMEM (2*FKSZ + 2*FVSZ + 128*PST*4)

__global__ void __launch_bounds__(256, 1)
flash_kernel(const float* __restrict__ qkv, float* __restrict__ o)
{
    extern __shared__ char fs[];
    const int tid = threadIdx.x;
    const int w = tid >> 5, lane = tid & 31;
    const int g = lane >> 2, tg = lane & 3;
    const int qt = blockIdx.x;
    const int z  = blockIdx.y;
    const int bb = z >> 3, hh = z & 7;

    char* Ks = fs;
    char* Vs = fs + 2 * FKSZ;
    float* Ps = (float*)(fs + 2 * FKSZ + 2 * FVSZ);
    const uint32_t Ksb = smem_u32(Ks), Vsb = smem_u32(Vs);

    const float* qbase = qkv + (size_t)bb * SS * (3 * EE) + hh * DH;

    uint32_t qfr[8][4];
    {
        int r0 = qt * 128 + w * 16 + g;
        const float* q0 = qbase + (size_t)r0 * (3 * EE);
        const float* q1 = q0 + (size_t)8 * (3 * EE);
        #pragma unroll
        for (int kk = 0; kk < 8; kk++) {
            qfr[kk][0] = __float_as_uint(0.125f * q0[kk * 8 + tg]);
            qfr[kk][1] = __float_as_uint(0.125f * q1[kk * 8 + tg]);
            qfr[kk][2] = __float_as_uint(0.125f * q0[kk * 8 + tg + 4]);
            qfr[kk][3] = __float_as_uint(0.125f * q1[kk * 8 + tg + 4]);
        }
    }

    float m0 = -1e30f, m1 = -1e30f, l0 = 0.f, l1 = 0.f;
    float oacc[8][4];
    #pragma unroll
    for (int i = 0; i < 8; i++)
        #pragma unroll
        for (int q = 0; q < 4; q++) oacc[i][q] = 0.f;

    auto loadKV = [&](int st, int j) {
        const float* kg = qbase + EE     + (size_t)(j * 128) * (3 * EE);
        const float* vg = qbase + 2 * EE + (size_t)(j * 128) * (3 * EE);
        #pragma unroll
        for (int i = 0; i < 8; i++) {
            int idx = tid + i * 256;
            int row = idx >> 4, c4 = (idx & 15) * 4;
            cpasync16(Ksb + st * FKSZ + (row * KST + c4) * 4,
                      kg + (size_t)row * (3 * EE) + c4);
            cpasync16(Vsb + st * FVSZ + (row * VST + c4) * 4,
                      vg + (size_t)row * (3 * EE) + c4);
        }
    };

    loadKV(0, 0); cp_commit();

    const int prow0 = (w * 16 + g) * PST;
    const int prow1 = prow0 + 8 * PST;

    for (int j = 0; j < 8; j++) {
        cp_wait0();
        __syncthreads();
        if (j + 1 < 8) { loadKV((j + 1) & 1, j + 1); cp_commit(); }

        float sacc[16][4];
        #pragma unroll
        for (int na = 0; na < 16; na++)
            #pragma unroll
            for (int q = 0; q < 4; q++) sacc[na][q] = 0.f;

        const float* Kt = (const float*)(Ks + (j & 1) * FKSZ);
        #pragma unroll
        for (int kk = 0; kk < 8; kk++) {
            #pragma unroll
            for (int na = 0; na < 16; na++) {
                int rn = na * 8 + g;
                uint32_t bfr[2];
                bfr[0] = __float_as_uint(Kt[rn * KST + kk * 8 + tg]);
                bfr[1] = __float_as_uint(Kt[rn * KST + kk * 8 + tg + 4]);
                mma_tf32(sacc[na], qfr[kk], bfr);
            }
        }

        float mx0 = -1e30f, mx1 = -1e30f;
        #pragma unroll
        for (int na = 0; na < 16; na++) {
            mx0 = fmaxf(mx0, fmaxf(sacc[na][0], sacc[na][1]));
            mx1 = fmaxf(mx1, fmaxf(sacc[na][2], sacc[na][3]));
        }
        mx0 = fmaxf(mx0, __shfl_xor_sync(0xffffffffu, mx0, 1));
        mx0 = fmaxf(mx0, __shfl_xor_sync(0xffffffffu, mx0, 2));
        mx1 = fmaxf(mx1, __shfl_xor_sync(0xffffffffu, mx1, 1));
        mx1 = fmaxf(mx1, __shfl_xor_sync(0xffffffffu, mx1, 2));
        float nm0 = fmaxf(m0, mx0), nm1 = fmaxf(m1, mx1);
        float a0 = expf(m0 - nm0), a1 = expf(m1 - nm1);
        float rs0 = 0.f, rs1 = 0.f;
        #pragma unroll
        for (int na = 0; na < 16; na++) {
            float p00 = expf(sacc[na][0] - nm0);
            float p01 = expf(sacc[na][1] - nm0);
            float p10 = expf(sacc[na][2] - nm1);
            float p11 = expf(sacc[na][3] - nm1);
            rs0 += p00 + p01; rs1 += p10 + p11;
            int col = na * 8 + tg * 2;
            *(float2*)(Ps + prow0 + col) = make_float2(roundtf(p00), roundtf(p01));
            *(float2*)(Ps + prow1 + col) = make_float2(roundtf(p10), roundtf(p11));
        }
        rs0 += __shfl_xor_sync(0xffffffffu, rs0, 1);
        rs0 += __shfl_xor_sync(0xffffffffu, rs0, 2);
        rs1 += __shfl_xor_sync(0xffffffffu, rs1, 1);
        rs1 += __shfl_xor_sync(0xffffffffu, rs1, 2);
        l0 = l0 * a0 + rs0; l1 = l1 * a1 + rs1;
        m0 = nm0; m1 = nm1;
        #pragma unroll
        for (int na2 = 0; na2 < 8; na2++) {
            oacc[na2][0] *= a0; oacc[na2][1] *= a0;
            oacc[na2][2] *= a1; oacc[na2][3] *= a1;
        }
        __syncthreads();

        const float* Vt = (const float*)(Vs + (j & 1) * FVSZ);
        #pragma unroll
        for (int kk = 0; kk < 16; kk++) {
            uint32_t pf[4];
            pf[0] = __float_as_uint(Ps[prow0 + kk * 8 + tg]);
            pf[1] = __float_as_uint(Ps[prow1 + kk * 8 + tg]);
            pf[2] = __float_as_uint(Ps[prow0 + kk * 8 + tg + 4]);
            pf[3] = __float_as_uint(Ps[prow1 + kk * 8 + tg + 4]);
            #pragma unroll
            for (int na2 = 0; na2 < 8; na2++) {
                uint32_t bf[2];
                bf[0] = __float_as_uint(Vt[(kk * 8 + tg) * VST + na2 * 8 + g]);
                bf[1] = __float_as_uint(Vt[(kk * 8 + tg + 4) * VST + na2 * 8 + g]);
                mma_tf32(oacc[na2], pf, bf);
            }
        }
    }

    float inv0 = 1.f / l0, inv1 = 1.f / l1;
    int r0 = qt * 128 + w * 16 + g;
    float* ob0 = o + (size_t)(bb * SS + r0) * EE + hh * DH;
    float* ob1 = ob0 + (size_t)8 * EE;
    #pragma unroll
    for (int na2 = 0; na2 < 8; na2++) {
        int col = na2 * 8 + tg * 2;
        *(float2*)(ob0 + col) = make_float2(roundtf(oacc[na2][0] * inv0),
                                            roundtf(oacc[na2][1] * inv0));
        *(float2*)(ob1 + col) = make_float2(roundtf(oacc[na2][2] * inv1),
                                            roundtf(oacc[na2][3] * inv1));
    }
}

// =====================================================================
// LayerNorm (R8 version, unchanged).
// =====================================================================
__global__ void ln_kernel(const float* __restrict__ x, const float* __restrict__ g,
                          const float* __restrict__ b, float* __restrict__ y)
{
    long long row = blockIdx.x;
    const float* xr = x + row * EE;
    int tid = threadIdx.x;
    float4 v = *(const float4*)(xr + tid * 4);
    float s  = v.x + v.y + v.z + v.w;
    float s2 = v.x * v.x + v.y * v.y + v.z * v.z + v.w * v.w;
    #pragma unroll
    for (int o = 16; o > 0; o >>= 1) {
        s  += __shfl_xor_sync(0xffffffffu, s, o);
        s2 += __shfl_xor_sync(0xffffffffu, s2, o);
    }
    __shared__ float ss[4], ssq[4];
    int w = tid >> 5, l = tid & 31;
    if (l == 0) { ss[w] = s; ssq[w] = s2; }
    __syncthreads();
    s  = ss[0] + ss[1] + ss[2] + ss[3];
    s2 = ssq[0] + ssq[1] + ssq[2] + ssq[3];
    float m   = s * (1.0f / EE);
    float var = s2 * (1.0f / EE) - m * m;
    float inv = rsqrtf(var + 1e-5f);
    float4 gg = *(const float4*)(g + tid * 4);
    float4 bb = *(const float4*)(b + tid * 4);
    float4 o4;
    o4.x = roundtf((v.x - m) * inv * gg.x + bb.x);
    o4.y = roundtf((v.y - m) * inv * gg.y + bb.y);
    o4.z = roundtf((v.z - m) * inv * gg.z + bb.z);
    o4.w = roundtf((v.w - m) * inv * gg.w + bb.w);
    *(float4*)(y + row * EE + tid * 4) = o4;
}

// =====================================================================
// Mamba-style recurrence v3b: feature=tid>>2, part=tid&3, shuffle
// reduction. FIX vs R15: the part-rotation is applied at WEIGHT LOAD
// time (addresses runtime, register index STATIC), so the step loop
// multiplies statically-indexed w[i] by dynamically-addressed shared
// h — no register-array spill.
// =====================================================================
__global__ void __cluster_dims__(8, 1, 1) __launch_bounds__(256, 1)
recur_kernel(const float* __restrict__ XP, const float* __restrict__ h0,
             const float* __restrict__ Wi2h, float* __restrict__ hout)
{
    __shared__ float hbuf[2 * EE];

    const int tid = threadIdx.x;
    const int b = blockIdx.x >> 3;
    const int r = blockIdx.x & 7;
    const int f = tid >> 2;            // feature 0..63
    const int p = tid & 3;             // k-part 0..3

    // Load rotated: w[i] corresponds to h element (i+p)&31 of this part.
    float4 w[32];
    {
        const float* wsrc = Wi2h + (long long)(r * 64 + f) * (2 * EE) + EE + p * 128;
        #pragma unroll
        for (int i = 0; i < 32; i++) {
            int j = (i + p) & 31;
            w[i] = *(const float4*)(wsrc + j * 4);
        }
    }
    if (tid < 128) *(float4*)(hbuf + tid * 4) = *(const float4*)(h0 + b * EE + tid * 4);

    uint32_t hb = (uint32_t)__cvta_generic_to_shared(hbuf);
    __syncthreads();
    asm volatile("barrier.cluster.arrive.aligned;" ::: "memory");
    asm volatile("barrier.cluster.wait.aligned;"   ::: "memory");

    const long long xpbase = (long long)b * SS * EE + r * 64 + f;

    for (int t = 0; t < SS; t++) {
        float xpv = 0.f;
        if (p == 0) xpv = __ldg(XP + xpbase + (long long)t * EE);

        // rotated base pointer: element i of the loop reads h[(i+p)&31].
        // Split the wrap at compile time: i < 28 is always wrap-free.
        const float* hr = hbuf + (t & 1) * EE + p * 128;
        const float* hr2 = hr + p * 4;          // start at rotation offset
        float a0 = 0.f, a1 = 0.f, a2 = 0.f, a3 = 0.f;
        #pragma unroll
        for (int i = 0; i < 32; i++) {
            // dynamic smem address, static register index
            const float* hp = (i < 28) ? (hr2 + i * 4)
                                       : (hr + (((i + p) & 31) * 4));
            float4 h4 = *(const float4*)hp;
            a0 += w[i].x * h4.x; a1 += w[i].y * h4.y;
            a2 += w[i].z * h4.z; a3 += w[i].w * h4.w;
        }
        float sm = (a0 + a1) + (a2 + a3);
        sm += __shfl_xor_sync(0xffffffffu, sm, 1);
        sm += __shfl_xor_sync(0xffffffffu, sm, 2);

        if (p == 0) {
            sm += xpv;
            float hn = tanhf(sm);
            hn = (hn > 0.f) ? hn : 0.f;
            uint32_t loff = hb + (uint32_t)((((t + 1) & 1) * EE + r * 64 + f) * 4);
            #pragma unroll
            for (int c = 0; c < 8; c++) {
                uint32_t ra;
                asm("mapa.shared::cluster.u32 %0, %1, %2;" : "=r"(ra) : "r"(loff), "r"(c));
                asm volatile("st.shared::cluster.f32 [%0], %1;" :: "r"(ra), "f"(hn));
            }
        }
        asm volatile("barrier.cluster.arrive.aligned;" ::: "memory");
        asm volatile("barrier.cluster.wait.aligned;"   ::: "memory");
    }
    if (p == 0) hout[b * EE + r * 64 + f] = hbuf[r * 64 + f];
}

// =====================================================================
// Head (unchanged).
// =====================================================================
__global__ void head_kernel(const float* __restrict__ hfin, const float* __restrict__ Wh2o,
                            const float* __restrict__ bh2o, const float* __restrict__ Wc,
                            const float* __restrict__ bc, float* __restrict__ out, int half)
{
    int b = blockIdx.x, tid = threadIdx.x;
    __shared__ float hrow[EE];
    __shared__ float red[EE];
    hrow[tid] = hfin[b * EE + tid];
    __syncthreads();
    const float* wr = Wh2o + (long long)tid * EE;
    float acc = bh2o[tid];
    #pragma unroll 8
    for (int f = 0; f < EE; f += 4) {
        float4 w4 = *(const float4*)(wr + f);
        acc += w4.x * hrow[f] + w4.y * hrow[f + 1] + w4.z * hrow[f + 2] + w4.w * hrow[f + 3];
    }
    red[tid] = acc * Wc[tid];
    __syncthreads();
    for (int s = 256; s > 0; s >>= 1) {
        if (tid < s) red[tid] += red[tid + s];
        __syncthreads();
    }
    if (tid == 0) {
        float lg = red[0] + bc[0];
        out[b] = lg;
        out[half + b] = 1.f / (1.f + expf(-lg));
    }
}

// ---------------- host-side launch helpers ----------------
static const int GEMM_SMEM = 3 * (128 * 32 * 4 + 128 * 32 * 4);  // 98304

template<int EPI, bool CVTA, bool RND>
static void run_mm(const float* A, const float* B, const float* bias, float* C,
                   int M, int N, int K, int lda, int ldb, int ldc)
{
    cudaFuncSetAttribute(gemm_mma<EPI, CVTA, RND>,
                         cudaFuncAttributeMaxDynamicSharedMemorySize, GEMM_SMEM);
    dim3 grid(N / 128, M / 128, 1);
    gemm_mma<EPI, CVTA, RND><<<grid, 256, GEMM_SMEM>>>(A, B, bias, C, M, N, K, lda, ldb, ldc);
}

extern "C" void kernel_launch(void* const* d_in, const int* in_sizes, int n_in,
                              void* d_out, int out_size)
{
    const float* bm   = (const float*)d_in[0];
    const float* h0   = (const float*)d_in[1];
    const float* Wp   = (const float*)d_in[2];
    const float* bp   = (const float*)d_in[3];
    const float* ln1g = (const float*)d_in[4];
    const float* ln1b = (const float*)d_in[5];
    const float* Wqkv = (const float*)d_in[6];
    const float* bqkv = (const float*)d_in[7];
    const float* Wo   = (const float*)d_in[8];
    const float* bo   = (const float*)d_in[9];
    const float* ln2g = (const float*)d_in[10];
    const float* ln2b = (const float*)d_in[11];
    const float* W1   = (const float*)d_in[12];
    const float* b1   = (const float*)d_in[13];
    const float* W2   = (const float*)d_in[14];
    const float* b2   = (const float*)d_in[15];
    const float* Wi2h = (const float*)d_in[16];
    const float* bi2h = (const float*)d_in[17];
    const float* Wh2o = (const float*)d_in[18];
    const float* bh2o = (const float*)d_in[19];
    const float* Wc   = (const float*)d_in[20];
    const float* bc   = (const float*)d_in[21];
    float* out = (float*)d_out;

    float *px, *pa, *pq, *po, *pf, *pxp, *ph, *pw;
    cudaGetSymbolAddress((void**)&px,  g_x);
    cudaGetSymbolAddress((void**)&pa,  g_a);
    cudaGetSymbolAddress((void**)&pq,  g_qkv);
    cudaGetSymbolAddress((void**)&po,  g_o);
    cudaGetSymbolAddress((void**)&pf,  g_f);
    cudaGetSymbolAddress((void**)&pxp, g_xp);
    cudaGetSymbolAddress((void**)&ph,  g_h);
    cudaGetSymbolAddress((void**)&pw,  g_wr);

    cudaFuncSetAttribute(flash_kernel,
                         cudaFuncAttributeMaxDynamicSharedMemorySize, FL_SMEM);

    // 0) single merged weight-prep launch
    round_all_kernel<<<(WR_TOTAL + 255) / 256, 256>>>(Wp, Wqkv, Wo, W1, W2, Wi2h, pw);

    // 1) modality projection (A raw f32 -> cvt; out = residual f32)
    run_mm<0, true, false>(bm, pw + OFF_WP, bp, px, MTOK, EE, DIN, DIN, DIN, EE);

    for (int l = 0; l < LL; l++) {
        const float* wqkv = pw + OFF_WQKV + (size_t)l * 3 * EE * EE;
        const float* bqk  = bqkv + (size_t)l * 3 * EE;
        const float* wo   = pw + OFF_WO + (size_t)l * EE * EE;
        const float* bo_  = bo   + (size_t)l * EE;
        const float* w1   = pw + OFF_W1 + (size_t)l * FF * EE;
        const float* b1_  = b1   + (size_t)l * FF;
        const float* w2   = pw + OFF_W2 + (size_t)l * EE * FF;
        const float* b2_  = b2   + (size_t)l * EE;

        // pre-LN attention (LN output rounded)
        ln_kernel<<<MTOK, 128>>>(px, ln1g + l * EE, ln1b + l * EE, pa);
        // QKV: A pre-rounded raw bits; output rounded (feeds flash)
        run_mm<0, false, true>(pa, wqkv, bqk, pq, MTOK, 3 * EE, EE, EE, EE, 3 * EE);

        // fused flash attention
        {
            dim3 grid(SS / 128, BB * HH);
            flash_kernel<<<grid, 256, FL_SMEM>>>(pq, po);
        }

        // x += O @ Wo^T + bo
        run_mm<2, false, false>(po, wo, bo_, px, MTOK, EE, EE, EE, EE, EE);

        // pre-LN FFN
        ln_kernel<<<MTOK, 128>>>(px, ln2g + l * EE, ln2b + l * EE, pa);
        run_mm<1, false, true>(pa, w1, b1_, pf, MTOK, FF, EE, EE, EE, FF);
        run_mm<2, false, false>(pf, w2, b2_, px, MTOK, EE, FF, FF, FF, EE);
    }

    // recurrence x-part (A = raw residual f32 -> cvt)
    run_mm<0, true, false>(px, pw + OFF_WI, bi2h, pxp, MTOK, EE, EE, EE, 2 * EE, EE);

    // sequential recurrence (persistent, clustered; original f32 Wi2h)
    recur_kernel<<<128, 256>>>(pxp, h0, Wi2h, ph);

    // head: logits + sigmoid
    head_kernel<<<BB, 512>>>(ph, Wh2o, bh2o, Wc, bc, out, out_size / 2);
}